// round 1
// baseline (speedup 1.0000x reference)
#include <cuda_runtime.h>
#include <cmath>

// ---------------- problem constants ----------------
#define HW   4096          // 64*64
#define SB   (64*HW)       // state batch stride (64 channels: 32 h + 32 c)
#define NB   4             // batch
#define T_IN 10
#define STEPS 18           // idx = 2..19
#define STATE_ELEMS (NB*64*HW)   // 1,048,576 floats = 4 MB
#define YBUF_ELEMS  (NB*32*HW)   // 524,288 floats = 2 MB

// ---------------- device scratch (no allocation allowed) ----------------
__device__ float g_sx0[3*2*STATE_ELEMS];   // per-layer cell-0 state, ping-pong across steps
__device__ float g_sz [3*2*STATE_ELEMS];   // per-layer z state, ping-pong across cells
__device__ float g_sx1[3*STATE_ELEMS];     // cell-1 state (intra-step only)
__device__ float g_sx2[3*STATE_ELEMS];     // cell-2 state (h needed for conv_y; c is dead)
__device__ float g_y  [2*3*YBUF_ELEMS];    // layer outputs, ping-pong across layers
__device__ float g_pred[STEPS*NB*HW];      // per-step predictions (closed-loop feedback)

__device__ __forceinline__ float sigf(float x) { return 1.0f / (1.0f + expf(-x)); }

// ---------------- fused conv + LSTM gating ----------------
// Computes gates = conv([x | h_x | h_z], w) + b (128 gate channels),
// then c_new = sig(f+0.01)*c_old + sig(i)*tanh(g);  h_new = sig(o)*tanh(c_new)
// Block: 16x16 pixels, each thread 1 pixel x 8 hidden channels (x4 gates = 32 accums).
// grid.z = batch(4) * hidden_chunk(4).
template<int K, int CINX>
__global__ __launch_bounds__(256) void conv_gate_kernel(
    const float* __restrict__ x, int x_bstride,
    const float* __restrict__ hx, const float* __restrict__ hz,
    const float* __restrict__ csrc,
    const float* __restrict__ w, const float* __restrict__ bias,
    float* __restrict__ dst)
{
    constexpr int KK  = K * K;
    constexpr int PAD = K / 2;
    constexpr int TS  = 16 + K - 1;
    constexpr int CIN = CINX + 64;

    __shared__ float tile[TS * TS];
    __shared__ float wsm[32 * KK];

    const int tx = threadIdx.x, ty = threadIdx.y;
    const int tid = ty * 16 + tx;
    const int b     = blockIdx.z >> 2;
    const int chunk = blockIdx.z & 3;
    const int gx0 = blockIdx.x * 16 - PAD;
    const int gy0 = blockIdx.y * 16 - PAD;

    float acc[32];
#pragma unroll
    for (int i = 0; i < 32; i++) acc[i] = 0.f;

    for (int c = 0; c < CIN; ++c) {
        const float* p;
        if (c < CINX)           p = x  + (long)b * x_bstride + c * HW;
        else if (c < CINX + 32) p = hx + (long)b * SB + (c - CINX) * HW;
        else                    p = hz + (long)b * SB + (c - CINX - 32) * HW;

        __syncthreads();
        for (int i = tid; i < TS * TS; i += 256) {
            int iy = i / TS, ix = i - iy * TS;
            int yy = gy0 + iy, xx = gx0 + ix;
            tile[i] = (yy >= 0 && yy < 64 && xx >= 0 && xx < 64) ? p[yy * 64 + xx] : 0.f;
        }
        // weights for this input channel, 32 gate channels handled by this block
        const float* wc = w + (long)c * KK;
        for (int i = tid; i < 32 * KK; i += 256) {
            int a = i / KK, tap = i - a * KK;
            int jj = a >> 2, g = a & 3;
            int gc = g * 32 + chunk * 8 + jj;   // gate-channel index in [0,128)
            wsm[i] = wc[(long)gc * CIN * KK + tap];
        }
        __syncthreads();

#pragma unroll
        for (int ky = 0; ky < K; ++ky)
#pragma unroll
        for (int kx = 0; kx < K; ++kx) {
            float v = tile[(ty + ky) * TS + (tx + kx)];
            const int tap = ky * K + kx;
#pragma unroll
            for (int a = 0; a < 32; a++) acc[a] = fmaf(v, wsm[a * KK + tap], acc[a]);
        }
    }

    const int pix = (blockIdx.y * 16 + ty) * 64 + (blockIdx.x * 16 + tx);
#pragma unroll
    for (int jj = 0; jj < 8; jj++) {
        int hid = chunk * 8 + jj;
        float gi = sigf(acc[jj * 4 + 0] + bias[hid]);
        float gf = sigf(acc[jj * 4 + 1] + bias[32 + hid] + 0.01f);   // FORGET_BIAS
        float gg = tanhf(acc[jj * 4 + 2] + bias[64 + hid]);
        float go = sigf(acc[jj * 4 + 3] + bias[96 + hid]);
        float cold = csrc[(long)b * SB + (32 + hid) * HW + pix];
        float cnew = gf * cold + gi * gg;
        float hnew = go * tanhf(cnew);
        dst[(long)b * SB + hid * HW + pix]        = hnew;
        dst[(long)b * SB + (32 + hid) * HW + pix] = cnew;
    }
}

// ---------------- 1x1 output conv: y = w_y @ [h_x2 | h_z2] + b_y ----------------
__global__ __launch_bounds__(256) void conv_y_kernel(
    const float* __restrict__ hx2, const float* __restrict__ hz2,
    const float* __restrict__ wy, const float* __restrict__ by,
    float* __restrict__ y)
{
    __shared__ float wsm[32 * 64];
    const int tid = threadIdx.x;
    for (int i = tid; i < 2048; i += 256) wsm[i] = wy[i];
    __syncthreads();

    const int b = blockIdx.y;
    const int pix = blockIdx.x * 256 + tid;

    float acc[32];
#pragma unroll
    for (int o = 0; o < 32; o++) acc[o] = by[o];

#pragma unroll 4
    for (int ic = 0; ic < 32; ++ic) {
        float v = hx2[(long)b * SB + ic * HW + pix];
#pragma unroll
        for (int o = 0; o < 32; o++) acc[o] = fmaf(v, wsm[o * 64 + ic], acc[o]);
    }
#pragma unroll 4
    for (int ic = 0; ic < 32; ++ic) {
        float v = hz2[(long)b * SB + ic * HW + pix];
#pragma unroll
        for (int o = 0; o < 32; o++) acc[o] = fmaf(v, wsm[o * 64 + 32 + ic], acc[o]);
    }
#pragma unroll
    for (int o = 0; o < 32; o++) y[(long)b * 32 * HW + o * HW + pix] = acc[o];
}

// ---------------- final 1x1 conv (32 -> 1), writes pred history + output ----------------
__global__ void final_kernel(const float* __restrict__ y, const float* __restrict__ wl,
                             float* __restrict__ pred, float* __restrict__ outp)
{
    const int i = blockIdx.x * 256 + threadIdx.x;   // over NB*HW = 16384
    const int b = i >> 12, pix = i & 4095;
    float a = 0.f;
#pragma unroll
    for (int oc = 0; oc < 32; ++oc) a = fmaf(wl[oc], y[(long)b * 32 * HW + oc * HW + pix], a);
    pred[i] = a;                                          // g_pred layout [step][B][HW]
    if (outp) outp[(long)b * 10 * HW + pix] = a;          // out layout [B][10][HW]
}

// ---------------- host orchestration (graph-capturable) ----------------
extern "C" void kernel_launch(void* const* d_in, const int* in_sizes, int n_in,
                              void* d_out, int out_size)
{
    const float* in     = (const float*)d_in[0];
    const float* w_x0   = (const float*)d_in[1];
    const float* b_x0   = (const float*)d_in[2];
    const float* w_z0   = (const float*)d_in[3];
    const float* b_z0   = (const float*)d_in[4];
    const float* w_y0   = (const float*)d_in[5];
    const float* b_y0   = (const float*)d_in[6];
    const float* w_x1   = (const float*)d_in[7];
    const float* b_x1   = (const float*)d_in[8];
    const float* w_z1   = (const float*)d_in[9];
    const float* b_z1   = (const float*)d_in[10];
    const float* w_y1   = (const float*)d_in[11];
    const float* b_y1   = (const float*)d_in[12];
    const float* w_last = (const float*)d_in[13];
    float* out = (float*)d_out;

    float *sx0, *szp, *sx1, *sx2, *yb, *pred;
    cudaGetSymbolAddress((void**)&sx0,  g_sx0);
    cudaGetSymbolAddress((void**)&szp,  g_sz);
    cudaGetSymbolAddress((void**)&sx1,  g_sx1);
    cudaGetSymbolAddress((void**)&sx2,  g_sx2);
    cudaGetSymbolAddress((void**)&yb,   g_y);
    cudaGetSymbolAddress((void**)&pred, g_pred);

    // zero recurrent state (deterministic per launch)
    cudaMemsetAsync(sx0, 0, sizeof(float) * 3 * 2 * STATE_ELEMS, 0);
    cudaMemsetAsync(szp, 0, sizeof(float) * 3 * 2 * STATE_ELEMS, 0);

    const dim3 blk(16, 16), grd(4, 4, 16);

    for (int step = 0; step < STEPS; ++step) {
        const int idx = step + 2;
        for (int l = 0; l < 3; ++l) {
            for (int s = 0; s < 3; ++s) {
                // ---- x input: layer 0 = frame/pred window, layers 1,2 = previous layer y
                const float* xptr; int xbs;
                if (l == 0) {
                    int t = idx - 2 + s;          // virtual frame index
                    if (t < T_IN) { xptr = in + (long)t * HW;              xbs = T_IN * HW; }
                    else          { xptr = pred + (long)(t - 3) * NB * HW; xbs = HW; }
                } else {
                    xptr = yb + (((l - 1) & 1) * 3 + s) * (long)YBUF_ELEMS;
                    xbs = 32 * HW;
                }
                // ---- x-state src/dst (sx[l][2] is dead; only sx[l][0] persists steps)
                float* srcx = (s == 0) ? sx0 + (l * 2 + (step & 1)) * (long)STATE_ELEMS
                            : (s == 1) ? sx0 + (l * 2 + ((step + 1) & 1)) * (long)STATE_ELEMS
                                       : sx1 + l * (long)STATE_ELEMS;
                float* dstx = (s == 0) ? sx0 + (l * 2 + ((step + 1) & 1)) * (long)STATE_ELEMS
                            : (s == 1) ? sx1 + l * (long)STATE_ELEMS
                                       : sx2 + l * (long)STATE_ELEMS;
                // ---- z-state ping-pong per cell
                const int k = step * 3 + s;
                float* srcz = szp + (l * 2 + (k & 1)) * (long)STATE_ELEMS;
                float* dstz = szp + (l * 2 + ((k + 1) & 1)) * (long)STATE_ELEMS;

                // ---- weights
                const float *wx, *bx, *wz, *bz, *wy, *by;
                if (l == 0) {
                    wx = w_x0 + (long)s * 128 * 65 * 9;   bx = b_x0 + s * 128;
                    wz = w_z0 + (long)s * 128 * 65 * 25;  bz = b_z0 + s * 128;
                    wy = w_y0 + (long)s * 32 * 64;        by = b_y0 + s * 32;
                } else {
                    int q = (l - 1) * 3 + s;
                    wx = w_x1 + (long)q * 128 * 96 * 9;   bx = b_x1 + q * 128;
                    wz = w_z1 + (long)q * 128 * 96 * 25;  bz = b_z1 + q * 128;
                    wy = w_y1 + (long)q * 32 * 64;        by = b_y1 + q * 32;
                }

                if (l == 0) {
                    conv_gate_kernel<3, 1><<<grd, blk>>>(xptr, xbs, srcx, srcz, srcx, wx, bx, dstx);
                    conv_gate_kernel<5, 1><<<grd, blk>>>(xptr, xbs, srcx, srcz, srcz, wz, bz, dstz);
                } else {
                    conv_gate_kernel<3, 32><<<grd, blk>>>(xptr, xbs, srcx, srcz, srcx, wx, bx, dstx);
                    conv_gate_kernel<5, 32><<<grd, blk>>>(xptr, xbs, srcx, srcz, srcz, wz, bz, dstz);
                }
                float* ydst = yb + ((l & 1) * 3 + s) * (long)YBUF_ELEMS;
                conv_y_kernel<<<dim3(16, 4), 256>>>(dstx, dstz, wy, by, ydst);
            }
        }
        // ys[-1] of layer 2 lives in ping-pong slot (2 & 1) = 0, cell 2
        float* ylast = yb + (0 * 3 + 2) * (long)YBUF_ELEMS;
        float* predp = pred + (long)step * NB * HW;
        float* outp  = (step >= 8) ? out + (long)(step - 8) * HW : nullptr;
        final_kernel<<<64, 256>>>(ylast, w_last, predp, outp);
    }
}

// round 2
// speedup vs baseline: 1.9426x; 1.9426x over previous
#include <cuda_runtime.h>
#include <cmath>
#include <cstdint>

// ---------------- problem constants ----------------
#define HW   4096          // 64*64
#define SB   (64*HW)       // state batch stride (64 channels: 32 h + 32 c)
#define NB   4             // batch
#define T_IN 10
#define STEPS 18           // idx = 2..19
#define STATE_ELEMS (NB*64*HW)
#define YBUF_ELEMS  (NB*32*HW)

// ---------------- device scratch ----------------
__device__ float g_sx0[3*2*STATE_ELEMS];
__device__ float g_sz [3*2*STATE_ELEMS];
__device__ float g_sx1[3*STATE_ELEMS];
__device__ float g_sx2[3*STATE_ELEMS];
__device__ float g_y  [2*3*YBUF_ELEMS];
__device__ float g_pred[STEPS*NB*HW];

// transposed weights: [set][cin][tap][gate'] with gate' = chunk*32 + j*4 + g
__device__ float g_wx0t[3*65*9*128];
__device__ float g_wz0t[3*65*25*128];
__device__ float g_wx1t[6*96*9*128];
__device__ float g_wz1t[6*96*25*128];

__device__ __forceinline__ float sigf(float x) { return 1.0f / (1.0f + expf(-x)); }

__device__ __forceinline__ unsigned sptr(const void* p) {
    return (unsigned)__cvta_generic_to_shared(p);
}
__device__ __forceinline__ void cpa4(unsigned d, const void* s, bool ok) {
    asm volatile("cp.async.ca.shared.global [%0], [%1], 4, %2;" :: "r"(d), "l"(s), "r"(ok ? 4 : 0));
}
__device__ __forceinline__ void cpa16(unsigned d, const void* s) {
    asm volatile("cp.async.cg.shared.global [%0], [%1], 16;" :: "r"(d), "l"(s));
}
#define CP_COMMIT() asm volatile("cp.async.commit_group;")
template<int N> __device__ __forceinline__ void cp_wait() {
    asm volatile("cp.async.wait_group %0;" :: "n"(N));
}
#define FFMA2(acc, a, b) asm("fma.rn.f32x2 %0, %1, %2, %0;" : "+l"(acc) : "l"(a), "l"(b))

// ---------------- weight pre-transpose ----------------
// dst[(((set*cin + ci)*kk + tap)<<7) + gp] = src[(((set*128 + gc)*cin + ci)*kk + tap]
// gp = chunk*32 + j*4 + g  <->  gc = g*32 + chunk*8 + j
__global__ void transpose_w(const float* __restrict__ src, float* __restrict__ dst,
                            int cin, int kk, long total)
{
    long i = (long)blockIdx.x * 256 + threadIdx.x;
    if (i >= total) return;
    int gp = (int)(i & 127);
    long r = i >> 7;
    int tap = (int)(r % kk); r /= kk;
    int ci  = (int)(r % cin);
    int set = (int)(r / cin);
    int chunk = gp >> 5, rem = gp & 31, j = rem >> 2, g = rem & 3;
    int gc = g * 32 + chunk * 8 + j;
    dst[i] = src[(((long)set * 128 + gc) * cin + ci) * kk + tap];
}

// ---------------- fused conv + LSTM gating (one branch) ----------------
template<int K, int CINX>
__device__ __forceinline__ void conv_branch(
    const float* __restrict__ x, int xbs,
    const float* __restrict__ hx, const float* __restrict__ hz,
    const float* __restrict__ cstate,
    const float* __restrict__ wt, const float* __restrict__ bias,
    float* __restrict__ dst,
    float* tileb, float* wb, int b, int chunk)
{
    constexpr int KK = K * K, PAD = K / 2, TS = 16 + K - 1, TSQ = TS * TS;
    constexpr int CIN = CINX + 64;
    const int tx = threadIdx.x, ty = threadIdx.y, tid = ty * 16 + tx;
    const int gx0 = blockIdx.x * 16 - PAD, gy0 = blockIdx.y * 16 - PAD;

    auto chanptr = [&](int c) -> const float* {
        if (c < CINX)            return x  + (long)b * xbs + c * HW;
        else if (c < CINX + 32)  return hx + (long)b * SB + (c - CINX) * HW;
        else                     return hz + (long)b * SB + (c - CINX - 32) * HW;
    };
    auto prefetch = [&](int c, int buf) {
        const float* p = chanptr(c);
        float* tb = tileb + buf * TSQ;
        for (int i = tid; i < TSQ; i += 256) {
            int iy = i / TS, ix = i - iy * TS;
            int yy = gy0 + iy, xx = gx0 + ix;
            bool ok = (yy >= 0 && yy < 64 && xx >= 0 && xx < 64);
            cpa4(sptr(tb + i), ok ? p + yy * 64 + xx : p, ok);
        }
        if (tid < KK * 8) {
            int tap = tid >> 3, off = tid & 7;
            const float* src = wt + (((long)c * KK + tap) << 7) + chunk * 32 + off * 4;
            cpa16(sptr(wb + buf * (KK * 32) + tap * 32 + off * 4), src);
        }
        CP_COMMIT();
    };

    unsigned long long acc[16];
#pragma unroll
    for (int i = 0; i < 16; i++) acc[i] = 0ull;

    prefetch(0, 0);
    for (int c = 0; c < CIN; ++c) {
        if (c + 1 < CIN) { prefetch(c + 1, (c + 1) % 3); cp_wait<1>(); }
        else             { cp_wait<0>(); }
        __syncthreads();
        const float* tb = tileb + (c % 3) * TSQ;
        const float* wp = wb + (c % 3) * (KK * 32);
#pragma unroll
        for (int ky = 0; ky < K; ++ky)
#pragma unroll
        for (int kx = 0; kx < K; ++kx) {
            float v = tb[(ty + ky) * TS + tx + kx];
            unsigned long long vv;
            asm("mov.b64 %0, {%1, %1};" : "=l"(vv) : "f"(v));
            const ulonglong2* wq = (const ulonglong2*)(wp + (ky * K + kx) * 32);
#pragma unroll
            for (int p = 0; p < 8; p++) {
                ulonglong2 w2 = wq[p];
                FFMA2(acc[2 * p],     vv, w2.x);
                FFMA2(acc[2 * p + 1], vv, w2.y);
            }
        }
    }

    const int pix = (blockIdx.y * 16 + ty) * 64 + blockIdx.x * 16 + tx;
#pragma unroll
    for (int j = 0; j < 8; j++) {
        float ai, af, ag, ao;
        asm("mov.b64 {%0, %1}, %2;" : "=f"(ai), "=f"(af) : "l"(acc[2 * j]));
        asm("mov.b64 {%0, %1}, %2;" : "=f"(ag), "=f"(ao) : "l"(acc[2 * j + 1]));
        int hid = chunk * 8 + j;
        float gi = sigf(ai + bias[hid]);
        float gf = sigf(af + bias[32 + hid] + 0.01f);    // FORGET_BIAS
        float gg = tanhf(ag + bias[64 + hid]);
        float go = sigf(ao + bias[96 + hid]);
        float cold = cstate[(long)b * SB + (32 + hid) * HW + pix];
        float cnew = gf * cold + gi * gg;
        dst[(long)b * SB + hid * HW + pix]        = go * tanhf(cnew);
        dst[(long)b * SB + (32 + hid) * HW + pix] = cnew;
    }
}

// ---------------- fused cell kernel: k3 (x-branch) + k5 (z-branch) ----------------
// grid (4,4,32): z<16 -> K=3 branch, z>=16 -> K=5 branch; z&15 = b*4+chunk
template<int CINX>
__global__ __launch_bounds__(256, 2) void cell_kernel(
    const float* __restrict__ x, int xbs,
    const float* __restrict__ srcx, const float* __restrict__ srcz,
    const float* __restrict__ wxt, const float* __restrict__ bx,
    const float* __restrict__ wzt, const float* __restrict__ bz,
    float* __restrict__ dstx, float* __restrict__ dstz)
{
    __shared__ float tileb[3 * 400];
    __shared__ __align__(16) float wb[3 * 800];
    int zz = blockIdx.z;
    int b = (zz & 15) >> 2, chunk = zz & 3;
    if (zz < 16)
        conv_branch<3, CINX>(x, xbs, srcx, srcz, srcx, wxt, bx, dstx, tileb, wb, b, chunk);
    else
        conv_branch<5, CINX>(x, xbs, srcx, srcz, srcz, wzt, bz, dstz, tileb, wb, b, chunk);
}

// ---------------- 1x1 output conv ----------------
__global__ __launch_bounds__(128) void conv_y_kernel(
    const float* __restrict__ hx2, const float* __restrict__ hz2,
    const float* __restrict__ wy, const float* __restrict__ by,
    float* __restrict__ y)
{
    __shared__ float wsm[32 * 64];
    const int tid = threadIdx.x;
    for (int i = tid; i < 2048; i += 128) wsm[i] = wy[i];
    __syncthreads();

    const int b = blockIdx.y;
    const int pix = blockIdx.x * 128 + tid;

    float acc[32];
#pragma unroll
    for (int o = 0; o < 32; o++) acc[o] = by[o];

#pragma unroll 4
    for (int ic = 0; ic < 32; ++ic) {
        float v = hx2[(long)b * SB + ic * HW + pix];
#pragma unroll
        for (int o = 0; o < 32; o++) acc[o] = fmaf(v, wsm[o * 64 + ic], acc[o]);
    }
#pragma unroll 4
    for (int ic = 0; ic < 32; ++ic) {
        float v = hz2[(long)b * SB + ic * HW + pix];
#pragma unroll
        for (int o = 0; o < 32; o++) acc[o] = fmaf(v, wsm[o * 64 + 32 + ic], acc[o]);
    }
#pragma unroll
    for (int o = 0; o < 32; o++) y[(long)b * 32 * HW + o * HW + pix] = acc[o];
}

// ---------------- final 1x1 conv (32 -> 1) ----------------
__global__ void final_kernel(const float* __restrict__ y, const float* __restrict__ wl,
                             float* __restrict__ pred, float* __restrict__ outp)
{
    const int i = blockIdx.x * 256 + threadIdx.x;   // NB*HW = 16384
    const int b = i >> 12, pix = i & 4095;
    float a = 0.f;
#pragma unroll
    for (int oc = 0; oc < 32; ++oc) a = fmaf(wl[oc], y[(long)b * 32 * HW + oc * HW + pix], a);
    pred[i] = a;
    if (outp) outp[(long)b * 10 * HW + pix] = a;
}

// ---------------- host orchestration ----------------
extern "C" void kernel_launch(void* const* d_in, const int* in_sizes, int n_in,
                              void* d_out, int out_size)
{
    const float* in     = (const float*)d_in[0];
    const float* w_x0   = (const float*)d_in[1];
    const float* b_x0   = (const float*)d_in[2];
    const float* w_z0   = (const float*)d_in[3];
    const float* b_z0   = (const float*)d_in[4];
    const float* w_y0   = (const float*)d_in[5];
    const float* b_y0   = (const float*)d_in[6];
    const float* w_x1   = (const float*)d_in[7];
    const float* b_x1   = (const float*)d_in[8];
    const float* w_z1   = (const float*)d_in[9];
    const float* b_z1   = (const float*)d_in[10];
    const float* w_y1   = (const float*)d_in[11];
    const float* b_y1   = (const float*)d_in[12];
    const float* w_last = (const float*)d_in[13];
    float* out = (float*)d_out;

    float *sx0, *szp, *sx1, *sx2, *yb, *pred, *wx0t, *wz0t, *wx1t, *wz1t;
    cudaGetSymbolAddress((void**)&sx0,  g_sx0);
    cudaGetSymbolAddress((void**)&szp,  g_sz);
    cudaGetSymbolAddress((void**)&sx1,  g_sx1);
    cudaGetSymbolAddress((void**)&sx2,  g_sx2);
    cudaGetSymbolAddress((void**)&yb,   g_y);
    cudaGetSymbolAddress((void**)&pred, g_pred);
    cudaGetSymbolAddress((void**)&wx0t, g_wx0t);
    cudaGetSymbolAddress((void**)&wz0t, g_wz0t);
    cudaGetSymbolAddress((void**)&wx1t, g_wx1t);
    cudaGetSymbolAddress((void**)&wz1t, g_wz1t);

    cudaMemsetAsync(sx0, 0, sizeof(float) * 3 * 2 * STATE_ELEMS, 0);
    cudaMemsetAsync(szp, 0, sizeof(float) * 3 * 2 * STATE_ELEMS, 0);

    // weight pre-transpose (amortized: ~13 MB of traffic)
    {
        long t;
        t = (long)3 * 65 * 9  * 128; transpose_w<<<(int)((t + 255) / 256), 256>>>(w_x0, wx0t, 65, 9,  t);
        t = (long)3 * 65 * 25 * 128; transpose_w<<<(int)((t + 255) / 256), 256>>>(w_z0, wz0t, 65, 25, t);
        t = (long)6 * 96 * 9  * 128; transpose_w<<<(int)((t + 255) / 256), 256>>>(w_x1, wx1t, 96, 9,  t);
        t = (long)6 * 96 * 25 * 128; transpose_w<<<(int)((t + 255) / 256), 256>>>(w_z1, wz1t, 96, 25, t);
    }

    const dim3 blk(16, 16), grd(4, 4, 32);

    for (int step = 0; step < STEPS; ++step) {
        const int idx = step + 2;
        for (int l = 0; l < 3; ++l) {
            for (int s = 0; s < 3; ++s) {
                const float* xptr; int xbs;
                if (l == 0) {
                    int t = idx - 2 + s;
                    if (t < T_IN) { xptr = in + (long)t * HW;              xbs = T_IN * HW; }
                    else          { xptr = pred + (long)(t - 3) * NB * HW; xbs = HW; }
                } else {
                    xptr = yb + (((l - 1) & 1) * 3 + s) * (long)YBUF_ELEMS;
                    xbs = 32 * HW;
                }
                float* srcx = (s == 0) ? sx0 + (l * 2 + (step & 1)) * (long)STATE_ELEMS
                            : (s == 1) ? sx0 + (l * 2 + ((step + 1) & 1)) * (long)STATE_ELEMS
                                       : sx1 + l * (long)STATE_ELEMS;
                float* dstx = (s == 0) ? sx0 + (l * 2 + ((step + 1) & 1)) * (long)STATE_ELEMS
                            : (s == 1) ? sx1 + l * (long)STATE_ELEMS
                                       : sx2 + l * (long)STATE_ELEMS;
                const int k = step * 3 + s;
                float* srcz = szp + (l * 2 + (k & 1)) * (long)STATE_ELEMS;
                float* dstz = szp + (l * 2 + ((k + 1) & 1)) * (long)STATE_ELEMS;

                const float *wxt, *bx, *wzt, *bz, *wy, *by;
                if (l == 0) {
                    wxt = wx0t + (long)s * 65 * 9 * 128;   bx = b_x0 + s * 128;
                    wzt = wz0t + (long)s * 65 * 25 * 128;  bz = b_z0 + s * 128;
                    wy  = w_y0 + (long)s * 32 * 64;        by = b_y0 + s * 32;
                } else {
                    int q = (l - 1) * 3 + s;
                    wxt = wx1t + (long)q * 96 * 9 * 128;   bx = b_x1 + q * 128;
                    wzt = wz1t + (long)q * 96 * 25 * 128;  bz = b_z1 + q * 128;
                    wy  = w_y1 + (long)q * 32 * 64;        by = b_y1 + q * 32;
                }

                if (l == 0)
                    cell_kernel<1><<<grd, blk>>>(xptr, xbs, srcx, srcz, wxt, bx, wzt, bz, dstx, dstz);
                else
                    cell_kernel<32><<<grd, blk>>>(xptr, xbs, srcx, srcz, wxt, bx, wzt, bz, dstx, dstz);

                float* ydst = yb + ((l & 1) * 3 + s) * (long)YBUF_ELEMS;
                conv_y_kernel<<<dim3(32, 4), 128>>>(dstx, dstz, wy, by, ydst);
            }
        }
        float* ylast = yb + (0 * 3 + 2) * (long)YBUF_ELEMS;
        float* predp = pred + (long)step * NB * HW;
        float* outp  = (step >= 8) ? out + (long)(step - 8) * HW : nullptr;
        final_kernel<<<64, 256>>>(ylast, w_last, predp, outp);
    }
}

// round 3
// speedup vs baseline: 2.1319x; 1.0974x over previous
#include <cuda_runtime.h>
#include <cmath>
#include <cstdint>

// ---------------- problem constants ----------------
#define HW   4096
#define SB   (64*HW)
#define NB   4
#define T_IN 10
#define STEPS 18
#define STATE_ELEMS (NB*64*HW)
#define YBUF_ELEMS  (NB*32*HW)

// ---------------- device scratch ----------------
__device__ float g_sx0[3*2*STATE_ELEMS];
__device__ float g_sz [3*2*STATE_ELEMS];
__device__ float g_sx1[3*STATE_ELEMS];
__device__ float g_sx2[3*STATE_ELEMS];
__device__ float g_y  [2*3*YBUF_ELEMS];
__device__ float g_pred[STEPS*NB*HW];

// transposed weights: [set][cin][tap][gate'] gate' = chunk*32 + j*4 + g
__device__ float g_wx0t[3*65*9*128];
__device__ float g_wz0t[3*65*25*128];
__device__ float g_wx1t[6*96*9*128];
__device__ float g_wz1t[6*96*25*128];

__device__ __forceinline__ float sigf(float x) { return 1.0f / (1.0f + expf(-x)); }

__device__ __forceinline__ unsigned sptr(const void* p) {
    return (unsigned)__cvta_generic_to_shared(p);
}
__device__ __forceinline__ void cpa4(unsigned d, const void* s, bool ok) {
    asm volatile("cp.async.ca.shared.global [%0], [%1], 4, %2;" :: "r"(d), "l"(s), "r"(ok ? 4 : 0));
}
__device__ __forceinline__ void cpa16(unsigned d, const void* s) {
    asm volatile("cp.async.cg.shared.global [%0], [%1], 16;" :: "r"(d), "l"(s));
}
#define CP_COMMIT() asm volatile("cp.async.commit_group;")
template<int N> __device__ __forceinline__ void cp_wait() {
    asm volatile("cp.async.wait_group %0;" :: "n"(N));
}
#define FFMA2(acc, a, b) asm("fma.rn.f32x2 %0, %1, %2, %0;" : "+l"(acc) : "l"(a), "l"(b))

// ---------------- fused weight pre-transpose (ONE launch) ----------------
__device__ __forceinline__ void transpose_one(const float* __restrict__ src,
                                              float* __restrict__ dst,
                                              int cin, int kk, long i)
{
    int gp = (int)(i & 127);
    long r = i >> 7;
    int tap = (int)(r % kk); r /= kk;
    int ci  = (int)(r % cin);
    int set = (int)(r / cin);
    int chunk = gp >> 5, rem = gp & 31, j = rem >> 2, g = rem & 3;
    int gc = g * 32 + chunk * 8 + j;
    dst[i] = src[(((long)set * 128 + gc) * cin + ci) * kk + tap];
}

#define NA ((long)3*65*9*128)
#define NBW ((long)3*65*25*128)
#define NC ((long)6*96*9*128)
#define ND ((long)6*96*25*128)

__global__ void transpose_all(const float* __restrict__ wx0, const float* __restrict__ wz0,
                              const float* __restrict__ wx1, const float* __restrict__ wz1,
                              float* __restrict__ dx0, float* __restrict__ dz0,
                              float* __restrict__ dx1, float* __restrict__ dz1)
{
    long i = (long)blockIdx.x * 256 + threadIdx.x;
    if (i < NA)                     { transpose_one(wx0, dx0, 65, 9,  i); return; }
    i -= NA;
    if (i < NBW)                    { transpose_one(wz0, dz0, 65, 25, i); return; }
    i -= NBW;
    if (i < NC)                     { transpose_one(wx1, dx1, 96, 9,  i); return; }
    i -= NC;
    if (i < ND)                     { transpose_one(wz1, dz1, 96, 25, i); }
}

// ---------------- fused conv + LSTM gating (one branch, 2 px/thread) ----------------
// Block: 256 threads (16x16), covers 32x16 pixels (thread owns x and x+16).
// Each thread: 8 hidden ch x 4 gates x 2 px = 64 accumulators (32 f32x2).
#define TSTRIDE 48
template<int K, int CINX>
__device__ __forceinline__ void conv_branch(
    const float* __restrict__ x, int xbs,
    const float* __restrict__ hx, const float* __restrict__ hz,
    const float* __restrict__ cstate,
    const float* __restrict__ wt, const float* __restrict__ bias,
    float* __restrict__ dst,
    float* tileb, float* wb, int b, int chunk, int xt, int yt)
{
    constexpr int KK = K * K, PAD = K / 2;
    constexpr int TSX = 32 + K - 1, TSY = 16 + K - 1;
    constexpr int CIN = CINX + 64;
    constexpr int WSZ = KK * 32;
    const int tx = threadIdx.x & 15, ty = threadIdx.x >> 4, tid = threadIdx.x;
    const int gx0 = xt * 32 - PAD, gy0 = yt * 16 - PAD;

    auto chanptr = [&](int c) -> const float* {
        if (c < CINX)            return x  + (long)b * xbs + c * HW;
        else if (c < CINX + 32)  return hx + (long)b * SB + (c - CINX) * HW;
        else                     return hz + (long)b * SB + (c - CINX - 32) * HW;
    };
    auto prefetch = [&](int c, int buf) {
        const float* p = chanptr(c);
        float* tb = tileb + buf * (20 * TSTRIDE);
#pragma unroll
        for (int i = tid; i < TSY * TSX; i += 256) {
            int iy = i / TSX, ix = i - iy * TSX;
            int yy = gy0 + iy, xx = gx0 + ix;
            bool ok = (yy >= 0 && yy < 64 && xx >= 0 && xx < 64);
            cpa4(sptr(tb + iy * TSTRIDE + ix), ok ? p + yy * 64 + xx : p, ok);
        }
        if (tid < KK * 8) {
            int tap = tid >> 3, off = tid & 7;
            const float* src = wt + (((long)c * KK + tap) << 7) + chunk * 32 + off * 4;
            cpa16(sptr(wb + buf * WSZ + tap * 32 + off * 4), src);
        }
        CP_COMMIT();
    };

    unsigned long long a0[16], a1[16];
#pragma unroll
    for (int i = 0; i < 16; i++) { a0[i] = 0ull; a1[i] = 0ull; }

    prefetch(0, 0);
    for (int c = 0; c < CIN; ++c) {
        if (c + 1 < CIN) { prefetch(c + 1, (c + 1) % 3); cp_wait<1>(); }
        else             { cp_wait<0>(); }
        __syncthreads();
        const float* tb = tileb + (c % 3) * (20 * TSTRIDE);
        const float* wp = wb + (c % 3) * WSZ;
#pragma unroll
        for (int ky = 0; ky < K; ++ky)
#pragma unroll
        for (int kx = 0; kx < K; ++kx) {
            float v0 = tb[(ty + ky) * TSTRIDE + tx + kx];
            float v1 = tb[(ty + ky) * TSTRIDE + tx + 16 + kx];
            unsigned long long vv0, vv1;
            asm("mov.b64 %0, {%1, %1};" : "=l"(vv0) : "f"(v0));
            asm("mov.b64 %0, {%1, %1};" : "=l"(vv1) : "f"(v1));
            const ulonglong2* wq = (const ulonglong2*)(wp + (ky * K + kx) * 32);
#pragma unroll
            for (int p = 0; p < 8; p++) {
                ulonglong2 w2 = wq[p];
                FFMA2(a0[2 * p],     vv0, w2.x);
                FFMA2(a0[2 * p + 1], vv0, w2.y);
                FFMA2(a1[2 * p],     vv1, w2.x);
                FFMA2(a1[2 * p + 1], vv1, w2.y);
            }
        }
    }

    const int pix0 = (yt * 16 + ty) * 64 + xt * 32 + tx;
#pragma unroll
    for (int j = 0; j < 8; j++) {
        int hid = chunk * 8 + j;
        float bi = bias[hid], bf = bias[32 + hid] + 0.01f, bg = bias[64 + hid], bo = bias[96 + hid];
#pragma unroll
        for (int px = 0; px < 2; px++) {
            float ai, af, ag, ao;
            unsigned long long lo = px ? a1[2 * j] : a0[2 * j];
            unsigned long long hi = px ? a1[2 * j + 1] : a0[2 * j + 1];
            asm("mov.b64 {%0, %1}, %2;" : "=f"(ai), "=f"(af) : "l"(lo));
            asm("mov.b64 {%0, %1}, %2;" : "=f"(ag), "=f"(ao) : "l"(hi));
            int pix = pix0 + px * 16;
            float gi = sigf(ai + bi);
            float gf = sigf(af + bf);
            float gg = tanhf(ag + bg);
            float go = sigf(ao + bo);
            float cold = cstate[(long)b * SB + (32 + hid) * HW + pix];
            float cnew = gf * cold + gi * gg;
            dst[(long)b * SB + hid * HW + pix]        = go * tanhf(cnew);
            dst[(long)b * SB + (32 + hid) * HW + pix] = cnew;
        }
    }
}

// ---------------- fused cell kernel ----------------
// 1D grid, 256 blocks. branch = (bid>>2)&1 so that bid and bid+148 (same-SM
// pair under the classic placement LUT) get opposite branches (148 flips bit 2).
template<int CINX>
__global__ __launch_bounds__(256, 2) void cell_kernel(
    const float* __restrict__ x, int xbs,
    const float* __restrict__ srcx, const float* __restrict__ srcz,
    const float* __restrict__ wxt, const float* __restrict__ bx,
    const float* __restrict__ wzt, const float* __restrict__ bz,
    float* __restrict__ dstx, float* __restrict__ dstz)
{
    __shared__ float tileb[3 * 20 * TSTRIDE];
    __shared__ __align__(16) float wb[3 * 800];
    const int bid = blockIdx.x;
    const int branch = (bid >> 2) & 1;
    const int r = (bid & 3) | ((bid >> 3) << 2);   // 7 bits -> 0..127
    const int xt = r & 1, yt = (r >> 1) & 3, b = (r >> 3) & 3, chunk = (r >> 5) & 3;
    if (branch == 0)
        conv_branch<3, CINX>(x, xbs, srcx, srcz, srcx, wxt, bx, dstx, tileb, wb, b, chunk, xt, yt);
    else
        conv_branch<5, CINX>(x, xbs, srcx, srcz, srcz, wzt, bz, dstz, tileb, wb, b, chunk, xt, yt);
}

// ---------------- 1x1 output conv ----------------
__global__ __launch_bounds__(128) void conv_y_kernel(
    const float* __restrict__ hx2, const float* __restrict__ hz2,
    const float* __restrict__ wy, const float* __restrict__ by,
    float* __restrict__ y)
{
    __shared__ float wsm[32 * 64];
    const int tid = threadIdx.x;
    for (int i = tid; i < 2048; i += 128) wsm[i] = wy[i];
    __syncthreads();

    const int b = blockIdx.y;
    const int pix = blockIdx.x * 128 + tid;

    float acc[32];
#pragma unroll
    for (int o = 0; o < 32; o++) acc[o] = by[o];

#pragma unroll 4
    for (int ic = 0; ic < 32; ++ic) {
        float v = hx2[(long)b * SB + ic * HW + pix];
#pragma unroll
        for (int o = 0; o < 32; o++) acc[o] = fmaf(v, wsm[o * 64 + ic], acc[o]);
    }
#pragma unroll 4
    for (int ic = 0; ic < 32; ++ic) {
        float v = hz2[(long)b * SB + ic * HW + pix];
#pragma unroll
        for (int o = 0; o < 32; o++) acc[o] = fmaf(v, wsm[o * 64 + 32 + ic], acc[o]);
    }
#pragma unroll
    for (int o = 0; o < 32; o++) y[(long)b * 32 * HW + o * HW + pix] = acc[o];
}

// ---------------- final 1x1 conv (32 -> 1) ----------------
__global__ void final_kernel(const float* __restrict__ y, const float* __restrict__ wl,
                             float* __restrict__ pred, float* __restrict__ outp)
{
    const int i = blockIdx.x * 256 + threadIdx.x;
    const int b = i >> 12, pix = i & 4095;
    float a = 0.f;
#pragma unroll
    for (int oc = 0; oc < 32; ++oc) a = fmaf(wl[oc], y[(long)b * 32 * HW + oc * HW + pix], a);
    pred[i] = a;
    if (outp) outp[(long)b * 10 * HW + pix] = a;
}

// ---------------- host orchestration ----------------
extern "C" void kernel_launch(void* const* d_in, const int* in_sizes, int n_in,
                              void* d_out, int out_size)
{
    const float* in     = (const float*)d_in[0];
    const float* w_x0   = (const float*)d_in[1];
    const float* b_x0   = (const float*)d_in[2];
    const float* w_z0   = (const float*)d_in[3];
    const float* b_z0   = (const float*)d_in[4];
    const float* w_y0   = (const float*)d_in[5];
    const float* b_y0   = (const float*)d_in[6];
    const float* w_x1   = (const float*)d_in[7];
    const float* b_x1   = (const float*)d_in[8];
    const float* w_z1   = (const float*)d_in[9];
    const float* b_z1   = (const float*)d_in[10];
    const float* w_y1   = (const float*)d_in[11];
    const float* b_y1   = (const float*)d_in[12];
    const float* w_last = (const float*)d_in[13];
    float* out = (float*)d_out;

    float *sx0, *szp, *sx1, *sx2, *yb, *pred, *wx0t, *wz0t, *wx1t, *wz1t;
    cudaGetSymbolAddress((void**)&sx0,  g_sx0);
    cudaGetSymbolAddress((void**)&szp,  g_sz);
    cudaGetSymbolAddress((void**)&sx1,  g_sx1);
    cudaGetSymbolAddress((void**)&sx2,  g_sx2);
    cudaGetSymbolAddress((void**)&yb,   g_y);
    cudaGetSymbolAddress((void**)&pred, g_pred);
    cudaGetSymbolAddress((void**)&wx0t, g_wx0t);
    cudaGetSymbolAddress((void**)&wz0t, g_wz0t);
    cudaGetSymbolAddress((void**)&wx1t, g_wx1t);
    cudaGetSymbolAddress((void**)&wz1t, g_wz1t);

    cudaMemsetAsync(sx0, 0, sizeof(float) * 3 * 2 * STATE_ELEMS, 0);
    cudaMemsetAsync(szp, 0, sizeof(float) * 3 * 2 * STATE_ELEMS, 0);

    {
        long total = NA + NBW + NC + ND;
        transpose_all<<<(int)((total + 255) / 256), 256>>>(w_x0, w_z0, w_x1, w_z1,
                                                           wx0t, wz0t, wx1t, wz1t);
    }

    for (int step = 0; step < STEPS; ++step) {
        const int idx = step + 2;
        for (int l = 0; l < 3; ++l) {
            for (int s = 0; s < 3; ++s) {
                const float* xptr; int xbs;
                if (l == 0) {
                    int t = idx - 2 + s;
                    if (t < T_IN) { xptr = in + (long)t * HW;              xbs = T_IN * HW; }
                    else          { xptr = pred + (long)(t - 3) * NB * HW; xbs = HW; }
                } else {
                    xptr = yb + (((l - 1) & 1) * 3 + s) * (long)YBUF_ELEMS;
                    xbs = 32 * HW;
                }
                float* srcx = (s == 0) ? sx0 + (l * 2 + (step & 1)) * (long)STATE_ELEMS
                            : (s == 1) ? sx0 + (l * 2 + ((step + 1) & 1)) * (long)STATE_ELEMS
                                       : sx1 + l * (long)STATE_ELEMS;
                float* dstx = (s == 0) ? sx0 + (l * 2 + ((step + 1) & 1)) * (long)STATE_ELEMS
                            : (s == 1) ? sx1 + l * (long)STATE_ELEMS
                                       : sx2 + l * (long)STATE_ELEMS;
                const int k = step * 3 + s;
                float* srcz = szp + (l * 2 + (k & 1)) * (long)STATE_ELEMS;
                float* dstz = szp + (l * 2 + ((k + 1) & 1)) * (long)STATE_ELEMS;

                const float *wxt, *bx, *wzt, *bz, *wy, *by;
                if (l == 0) {
                    wxt = wx0t + (long)s * 65 * 9 * 128;   bx = b_x0 + s * 128;
                    wzt = wz0t + (long)s * 65 * 25 * 128;  bz = b_z0 + s * 128;
                    wy  = w_y0 + (long)s * 32 * 64;        by = b_y0 + s * 32;
                } else {
                    int q = (l - 1) * 3 + s;
                    wxt = wx1t + (long)q * 96 * 9 * 128;   bx = b_x1 + q * 128;
                    wzt = wz1t + (long)q * 96 * 25 * 128;  bz = b_z1 + q * 128;
                    wy  = w_y1 + (long)q * 32 * 64;        by = b_y1 + q * 32;
                }

                if (l == 0)
                    cell_kernel<1><<<256, 256>>>(xptr, xbs, srcx, srcz, wxt, bx, wzt, bz, dstx, dstz);
                else
                    cell_kernel<32><<<256, 256>>>(xptr, xbs, srcx, srcz, wxt, bx, wzt, bz, dstx, dstz);

                float* ydst = yb + ((l & 1) * 3 + s) * (long)YBUF_ELEMS;
                conv_y_kernel<<<dim3(32, 4), 128>>>(dstx, dstz, wy, by, ydst);
            }
        }
        float* ylast = yb + (0 * 3 + 2) * (long)YBUF_ELEMS;
        float* predp = pred + (long)step * NB * HW;
        float* outp  = (step >= 8) ? out + (long)(step - 8) * HW : nullptr;
        final_kernel<<<64, 256>>>(ylast, w_last, predp, outp);
    }
}